// round 1
// baseline (speedup 1.0000x reference)
#include <cuda_runtime.h>

// Problem constants (match reference)
#define NUM_CH   5
#define CROP_LO  70      // D//2 - 16, D = 173
#define CROP_N   32
#define CUBES    5
#define LATO     11      // 2*CUBES+1
#define RES2     0.0625f // RES*RES

__global__ void zero_out_kernel(float4* __restrict__ out, int n4) {
    int i = blockIdx.x * blockDim.x + threadIdx.x;
    if (i < n4) out[i] = make_float4(0.f, 0.f, 0.f, 0.f);
}

// One block (128 threads) per atom. Separable Gaussian: per-axis exp tables
// in smem, then scatter only the cells inside the 32^3 crop window.
__global__ void __launch_bounds__(128) splat_kernel(
    const float* __restrict__ coords,        // [B, N, 3]
    const int*   __restrict__ atoms_channel, // [B, N]
    const float* __restrict__ radius,        // [B, N]
    float* __restrict__ out,                 // [B, NUM_CH, 32, 32, 32]
    int n_per_batch)                         // N
{
    const int atom = blockIdx.x;
    const int b = atom / n_per_batch;
    const int tid = threadIdx.x;

    __shared__ float ex[3][LATO];
    __shared__ float s_scaled[3];
    __shared__ int   s_base[3];
    __shared__ float s_coef;    // 0.5 * RES^2 / r^2
    __shared__ int   s_chan;

    if (tid == 0) {
        float r = radius[atom];
        s_coef = 0.5f * RES2 / (r * r);
        s_chan = atoms_channel[atom];
    }
    if (tid < 3) {
        float c = coords[atom * 3 + tid];
        // scaled = (c + BOX)/RES + (CUBES+1) ; /0.25 == *4 exactly
        float s = (c + 20.0f) * 4.0f + 6.0f;
        s_scaled[tid] = s;
        s_base[tid] = (int)floorf(s) - CUBES;  // lowest touched cell
    }
    __syncthreads();

    if (tid < 3 * LATO) {
        int axis = tid / LATO;
        int o    = tid % LATO;
        float d  = s_scaled[axis] - (float)(s_base[axis] + o) - 0.5f;
        ex[axis][o] = expf(-s_coef * d * d);
    }
    __syncthreads();

    const int bx = s_base[0], by = s_base[1], bz = s_base[2];

    // Clip splat box against the crop window [CROP_LO, CROP_LO+32)
    int x0 = max(0, CROP_LO - bx),            y0 = max(0, CROP_LO - by),            z0 = max(0, CROP_LO - bz);
    int x1 = min(LATO - 1, CROP_LO + CROP_N - 1 - bx);
    int y1 = min(LATO - 1, CROP_LO + CROP_N - 1 - by);
    int z1 = min(LATO - 1, CROP_LO + CROP_N - 1 - bz);
    int nx = x1 - x0 + 1, ny = y1 - y0 + 1, nz = z1 - z0 + 1;
    if (nx <= 0 || ny <= 0 || nz <= 0) return;   // splat misses the crop

    const int nyz = ny * nz;
    const int ntot = nx * nyz;
    float* __restrict__ out_bc = out + (size_t)(b * NUM_CH + s_chan) * (CROP_N * CROP_N * CROP_N);

    for (int k = tid; k < ntot; k += blockDim.x) {
        int ox  = k / nyz;
        int rem = k - ox * nyz;
        int oy  = rem / nz;
        int oz  = rem - oy * nz;
        ox += x0; oy += y0; oz += z0;
        int cx = bx + ox - CROP_LO;
        int cy = by + oy - CROP_LO;
        int cz = bz + oz - CROP_LO;
        float v = ex[0][ox] * ex[1][oy] * ex[2][oz];
        atomicAdd(&out_bc[(cx * CROP_N + cy) * CROP_N + cz], v);
    }
}

extern "C" void kernel_launch(void* const* d_in, const int* in_sizes, int n_in,
                              void* d_out, int out_size) {
    const float* coords        = (const float*)d_in[0]; // [B,N,3]
    const int*   atoms_channel = (const int*)d_in[1];   // [B,N]
    const float* radius        = (const float*)d_in[2]; // [B,N]
    float* out = (float*)d_out;

    int n_atoms = in_sizes[1];                               // B*N
    int B = out_size / (NUM_CH * CROP_N * CROP_N * CROP_N);  // 8
    int n_per_batch = n_atoms / B;                           // 64

    // Zero the output (harness poisons it)
    int n4 = out_size / 4;
    zero_out_kernel<<<(n4 + 255) / 256, 256>>>((float4*)out, n4);

    // One block per atom
    splat_kernel<<<n_atoms, 128>>>(coords, atoms_channel, radius, out, n_per_batch);
}

// round 2
// speedup vs baseline: 1.0074x; 1.0074x over previous
#include <cuda_runtime.h>

// Problem constants (match reference)
#define NUM_CH   5
#define CROP_LO  70      // D//2 - 16, D = 173
#define CROP_HI  101     // CROP_LO + 32 - 1
#define CROP_N   32
#define CUBES    5
#define LATO     11      // 2*CUBES+1
#define RES2     0.0625f // RES*RES

// One WARP per atom. No shared memory, no __syncthreads.
// Fused per-cell Gaussian via MUFU __expf; index math via exact
// float-reciprocal division (valid for k < 2048, divisor <= 121).
__global__ void __launch_bounds__(128) splat_kernel(
    const float* __restrict__ coords,        // [B, N, 3]
    const int*   __restrict__ atoms_channel, // [B, N]
    const float* __restrict__ radius,        // [B, N]
    float* __restrict__ out,                 // [B, NUM_CH, 32, 32, 32]
    int n_per_batch, int n_atoms)
{
    const int warp = (blockIdx.x * blockDim.x + threadIdx.x) >> 5;
    const int lane = threadIdx.x & 31;
    if (warp >= n_atoms) return;
    const int atom = warp;
    const int b = atom / n_per_batch;

    // Uniform per-warp scalar loads (L1/L2 resident after first touch)
    const float cx = coords[3 * atom + 0];
    const float cy = coords[3 * atom + 1];
    const float cz = coords[3 * atom + 2];
    const float r  = radius[atom];
    const int   ch = atoms_channel[atom];

    // scaled = (c + BOX)/RES + (CUBES+1); /0.25 == *4 exactly
    const float sx = (cx + 20.0f) * 4.0f + 6.0f;
    const float sy = (cy + 20.0f) * 4.0f + 6.0f;
    const float sz = (cz + 20.0f) * 4.0f + 6.0f;
    const int bx = (int)floorf(sx) - CUBES;   // lowest touched cell per axis
    const int by = (int)floorf(sy) - CUBES;
    const int bz = (int)floorf(sz) - CUBES;
    // distance (voxels) from atom to center of cell (b? + o?):  f? - o?
    const float fx = sx - (float)bx - 0.5f;
    const float fy = sy - (float)by - 0.5f;
    const float fz = sz - (float)bz - 0.5f;

    // Clip splat box against crop window [CROP_LO, CROP_HI]
    const int x0 = max(0, CROP_LO - bx), x1 = min(LATO - 1, CROP_HI - bx);
    const int y0 = max(0, CROP_LO - by), y1 = min(LATO - 1, CROP_HI - by);
    const int z0 = max(0, CROP_LO - bz), z1 = min(LATO - 1, CROP_HI - bz);
    const int nx = x1 - x0 + 1, ny = y1 - y0 + 1, nz = z1 - z0 + 1;
    if (nx <= 0 || ny <= 0 || nz <= 0) return;   // entire splat misses the crop

    const int nyz  = ny * nz;
    const int ntot = nx * nyz;
    const float rnyz = 1.0f / (float)nyz;
    const float rnz  = 1.0f / (float)nz;

    const float coef = 0.5f * RES2 / (r * r);
    // base pointer at clipped-box origin inside this (b, ch) volume
    float* __restrict__ outp = out
        + (size_t)(b * NUM_CH + ch) * (CROP_N * CROP_N * CROP_N)
        + ((bx + x0 - CROP_LO) * CROP_N + (by + y0 - CROP_LO)) * CROP_N
        + (bz + z0 - CROP_LO);

    for (int k = lane; k < ntot; k += 32) {
        // exact small-integer division via fp32 (k < 1331, divisors <= 121)
        int ox  = (int)(((float)k + 0.5f) * rnyz);
        int rem = k - ox * nyz;
        int oy  = (int)(((float)rem + 0.5f) * rnz);
        int oz  = rem - oy * nz;
        float dx = fx - (float)(ox + x0);
        float dy = fy - (float)(oy + y0);
        float dz = fz - (float)(oz + z0);
        float d2 = fmaf(dx, dx, fmaf(dy, dy, dz * dz));
        float v  = __expf(-coef * d2);
        atomicAdd(&outp[(ox * CROP_N + oy) * CROP_N + oz], v);
    }
}

extern "C" void kernel_launch(void* const* d_in, const int* in_sizes, int n_in,
                              void* d_out, int out_size) {
    const float* coords        = (const float*)d_in[0]; // [B,N,3]
    const int*   atoms_channel = (const int*)d_in[1];   // [B,N]
    const float* radius        = (const float*)d_in[2]; // [B,N]
    float* out = (float*)d_out;

    int n_atoms = in_sizes[1];                               // B*N
    int B = out_size / (NUM_CH * CROP_N * CROP_N * CROP_N);  // 8
    int n_per_batch = n_atoms / B;                           // 64

    // Zero the output (harness poisons it) — graph memset node
    cudaMemsetAsync(out, 0, (size_t)out_size * sizeof(float));

    // One warp per atom, 4 warps per block
    int warps_per_block = 4;
    int blocks = (n_atoms + warps_per_block - 1) / warps_per_block;
    splat_kernel<<<blocks, warps_per_block * 32>>>(
        coords, atoms_channel, radius, out, n_per_batch, n_atoms);
}